// round 3
// baseline (speedup 1.0000x reference)
#include <cuda_runtime.h>
#include <cstdint>

// Problem constants (fixed by the dataset)
#define B 8
#define N 2048
#define IN_F 512
#define OUT_F 128

// Scratch (allocation-free rule: __device__ globals)
__device__ float g_w1[IN_F];
__device__ float g_w2[IN_F];
__device__ float g_x[B * N];    // x[b,i] = emb1[b,i,:] . w1
__device__ float g_y[B * N];    // y[b,i] = emb1[b,i,:] . w2
__device__ float g_xm[B * N];   // act ? x : -1e30
__device__ float g_ym[B * N];   // act ? y : -1e30
__device__ float g_scale[B];

// K1: w1 = W^T a1, w2 = W^T a2.  W is [OUT_F, IN_F] row-major.
__global__ void k_wproj(const float* __restrict__ W,
                        const float* __restrict__ a1,
                        const float* __restrict__ a2) {
    int f = blockIdx.x * blockDim.x + threadIdx.x;  // 0..511
    if (f >= IN_F) return;
    float s1 = 0.f, s2 = 0.f;
#pragma unroll 8
    for (int o = 0; o < OUT_F; o++) {
        float w = __ldg(W + (size_t)o * IN_F + f);
        s1 = fmaf(w, __ldg(a1 + o), s1);
        s2 = fmaf(w, __ldg(a2 + o), s2);
    }
    g_w1[f] = s1;
    g_w2[f] = s2;
}

// K2: per-row dual dot product. One warp per row (row = b*N + i).
__global__ void __launch_bounds__(256) k_xy(const float* __restrict__ emb) {
    int gwarp = (blockIdx.x * blockDim.x + threadIdx.x) >> 5;
    int lane  = threadIdx.x & 31;
    if (gwarp >= B * N) return;

    const float4* row = reinterpret_cast<const float4*>(emb + (size_t)gwarp * IN_F);
    const float4* w1  = reinterpret_cast<const float4*>(g_w1);
    const float4* w2  = reinterpret_cast<const float4*>(g_w2);

    float s1 = 0.f, s2 = 0.f;
#pragma unroll
    for (int k = 0; k < IN_F / 4 / 32; k++) {  // 4 float4 per lane
        int idx = lane + 32 * k;
        float4 e = row[idx];
        float4 v1 = w1[idx];
        float4 v2 = w2[idx];
        s1 = fmaf(e.x, v1.x, fmaf(e.y, v1.y, fmaf(e.z, v1.z, fmaf(e.w, v1.w, s1))));
        s2 = fmaf(e.x, v2.x, fmaf(e.y, v2.y, fmaf(e.z, v2.z, fmaf(e.w, v2.w, s2))));
    }
#pragma unroll
    for (int off = 16; off; off >>= 1) {
        s1 += __shfl_down_sync(0xffffffffu, s1, off);
        s2 += __shfl_down_sync(0xffffffffu, s2, off);
    }
    if (lane == 0) {
        g_x[gwarp] = s1;
        g_y[gwarp] = s2;
    }
}

// K3: per batch, stable descending rank of y among valid columns; build
// sentinel-encoded xm/ym arrays and the per-batch scale.
// grid = (N/128, B), block = 128
__global__ void __launch_bounds__(128) k_select(const int* __restrict__ n_src,
                                                const int* __restrict__ ns_tgt) {
    int b = blockIdx.y;
    __shared__ float ys[N];
    int ns   = ns_tgt[b];
    int nsrc = n_src[b];
    int kb   = (int)((float)nsrc * 0.4f);  // float32 mul + trunc, matches ref

    for (int l = threadIdx.x; l < N; l += 128)
        ys[l] = g_y[b * N + l];
    __syncthreads();

    int j = blockIdx.x * 128 + threadIdx.x;
    float yj = ys[j];
    int cnt = 0;
    if (j < ns) {
#pragma unroll 4
        for (int l = 0; l < ns; l++) {
            float v = ys[l];
            cnt += (v > yj);
            cnt += (v == yj) & (l < j);  // stable-sort tie break
        }
    }
    bool act = (j < ns) && (cnt < kb) && (j < nsrc);
    float xj = g_x[b * N + j];
    g_xm[b * N + j] = act ? xj : -1e30f;
    g_ym[b * N + j] = act ? yj : -1e30f;

    if (blockIdx.x == 0 && threadIdx.x == 0)
        g_scale[b] = 1.0f / ((float)nsrc * 0.4f);
}

// K4: materialize the output. One block per output row, float4 stores.
// out[b,i,j] = (xm[j]+ym[i] > 0) ? scale_b * tanh(max(0, x_i+y_j) * 0.125) : 0
__global__ void __launch_bounds__(256) k_out(float* __restrict__ out) {
    int row = blockIdx.x;        // 0 .. B*N-1
    int b   = row >> 11;         // N = 2048
    float xi  = g_x[row];
    float ymi = g_ym[row];
    float sc  = g_scale[b];

    const float4* xm4 = reinterpret_cast<const float4*>(g_xm + b * N);
    const float4* yy4 = reinterpret_cast<const float4*>(g_y + b * N);
    float4* o4 = reinterpret_cast<float4*>(out + (size_t)row * N);

#pragma unroll
    for (int s = 0; s < 2; s++) {
        int t = threadIdx.x + s * 256;   // 512 float4 per row
        float4 xm = xm4[t];
        float4 yy = yy4[t];
        float4 r;
        r.x = (xm.x + ymi > 0.f) ? sc * tanhf(fmaxf(xi + yy.x, 0.f) * 0.125f) : 0.f;
        r.y = (xm.y + ymi > 0.f) ? sc * tanhf(fmaxf(xi + yy.y, 0.f) * 0.125f) : 0.f;
        r.z = (xm.z + ymi > 0.f) ? sc * tanhf(fmaxf(xi + yy.z, 0.f) * 0.125f) : 0.f;
        r.w = (xm.w + ymi > 0.f) ? sc * tanhf(fmaxf(xi + yy.w, 0.f) * 0.125f) : 0.f;
        o4[t] = r;
    }
}

extern "C" void kernel_launch(void* const* d_in, const int* in_sizes, int n_in,
                              void* d_out, int out_size) {
    const float* emb1  = (const float*)d_in[0];
    const float* W     = (const float*)d_in[1];
    const float* a1    = (const float*)d_in[2];
    const float* a2    = (const float*)d_in[3];
    const int*   n_src = (const int*)d_in[4];
    const int*   nstgt = (const int*)d_in[5];
    float* out = (float*)d_out;

    k_wproj<<<2, 256>>>(W, a1, a2);
    k_xy<<<(B * N * 32 + 255) / 256, 256>>>(emb1);
    k_select<<<dim3(N / 128, B), 128>>>(n_src, nstgt);
    k_out<<<B * N, 256>>>(out);
}

// round 4
// speedup vs baseline: 1.5837x; 1.5837x over previous
#include <cuda_runtime.h>
#include <cstdint>

// Problem constants (fixed by the dataset)
#define B 8
#define N 2048
#define IN_F 512
#define OUT_F 128

// Scratch (allocation-free rule: __device__ globals), 16B-aligned for float4
__device__ __align__(16) float g_w1[IN_F];
__device__ __align__(16) float g_w2[IN_F];
__device__ __align__(16) float g_x8[B * N];   // 0.125 * (emb1[b,i,:] . w1)
__device__ __align__(16) float g_y8[B * N];   // 0.125 * (emb1[b,i,:] . w2)
__device__ __align__(16) float g_xm[B * N];   // act ? x8 : -1e30
__device__ __align__(16) float g_ym[B * N];   // act ? y8 : -1e30
__device__ float g_scale[B];

__device__ __forceinline__ float tanh_fast(float x) {
    float r;
    asm("tanh.approx.f32 %0, %1;" : "=f"(r) : "f"(x));
    return r;
}

// K1: w1 = W^T a1, w2 = W^T a2.  W is [OUT_F, IN_F] row-major.
// grid 16, block 128: f = bid*32 + lane, o-dim split 4 ways across warps.
__global__ void __launch_bounds__(128) k_wproj(const float* __restrict__ W,
                                               const float* __restrict__ a1,
                                               const float* __restrict__ a2) {
    int lane = threadIdx.x & 31;
    int oq   = threadIdx.x >> 5;                 // 0..3
    int f    = blockIdx.x * 32 + lane;           // 0..511
    float s1 = 0.f, s2 = 0.f;
#pragma unroll 8
    for (int o = oq * 32; o < oq * 32 + 32; o++) {
        float w = __ldg(W + (size_t)o * IN_F + f);
        s1 = fmaf(w, __ldg(a1 + o), s1);
        s2 = fmaf(w, __ldg(a2 + o), s2);
    }
    __shared__ float p1[128], p2[128];
    p1[threadIdx.x] = s1;
    p2[threadIdx.x] = s2;
    __syncthreads();
    if (threadIdx.x < 32) {
        float r1 = p1[lane] + p1[lane + 32] + p1[lane + 64] + p1[lane + 96];
        float r2 = p2[lane] + p2[lane + 32] + p2[lane + 64] + p2[lane + 96];
        g_w1[f] = r1;
        g_w2[f] = r2;
    }
}

// K2: per-row dual dot product, stored pre-scaled by 0.125 (exact pow2).
__global__ void __launch_bounds__(256) k_xy(const float* __restrict__ emb) {
    int gwarp = (blockIdx.x * blockDim.x + threadIdx.x) >> 5;
    int lane  = threadIdx.x & 31;
    if (gwarp >= B * N) return;

    const float4* row = reinterpret_cast<const float4*>(emb + (size_t)gwarp * IN_F);
    const float4* w1  = reinterpret_cast<const float4*>(g_w1);
    const float4* w2  = reinterpret_cast<const float4*>(g_w2);

    float s1 = 0.f, s2 = 0.f;
#pragma unroll
    for (int k = 0; k < IN_F / 4 / 32; k++) {
        int idx = lane + 32 * k;
        float4 e  = row[idx];
        float4 v1 = w1[idx];
        float4 v2 = w2[idx];
        s1 = fmaf(e.x, v1.x, fmaf(e.y, v1.y, fmaf(e.z, v1.z, fmaf(e.w, v1.w, s1))));
        s2 = fmaf(e.x, v2.x, fmaf(e.y, v2.y, fmaf(e.z, v2.z, fmaf(e.w, v2.w, s2))));
    }
#pragma unroll
    for (int off = 16; off; off >>= 1) {
        s1 += __shfl_down_sync(0xffffffffu, s1, off);
        s2 += __shfl_down_sync(0xffffffffu, s2, off);
    }
    if (lane == 0) {
        g_x8[gwarp] = s1 * 0.125f;
        g_y8[gwarp] = s2 * 0.125f;
    }
}

// K3: stable descending rank of y among valid columns; sentinel arrays.
// grid (N/64, B), block 256: 4 threads per column j, interleaved stride-4 scan.
__global__ void __launch_bounds__(256) k_select(const int* __restrict__ n_src,
                                                const int* __restrict__ ns_tgt) {
    int b = blockIdx.y;
    __shared__ float ys[N];
    int ns   = ns_tgt[b];
    int nsrc = n_src[b];
    int kb   = (int)((float)nsrc * 0.4f);   // float32 mul + trunc, matches ref

    for (int l = threadIdx.x; l < N; l += 256)
        ys[l] = g_y8[b * N + l];
    __syncthreads();

    int q  = threadIdx.x & 3;
    int jj = threadIdx.x >> 2;               // 0..63
    int j  = blockIdx.x * 64 + jj;
    float yj = ys[j];
    int cnt = 0;
#pragma unroll 4
    for (int l = q; l < ns; l += 4) {
        float v = ys[l];
        cnt += (v > yj);
        cnt += (v == yj) & (l < j);           // stable-sort tie break
    }
    // combine the 4 partial counts (lanes jj*4+q are consecutive in the warp)
    cnt += __shfl_xor_sync(0xffffffffu, cnt, 1);
    cnt += __shfl_xor_sync(0xffffffffu, cnt, 2);

    if (q == 0) {
        bool act = (j < ns) && (cnt < kb) && (j < nsrc);
        float xj = g_x8[b * N + j];
        g_xm[b * N + j] = act ? xj : -1e30f;
        g_ym[b * N + j] = act ? yj : -1e30f;
    }
    if (blockIdx.x == 0 && threadIdx.x == 0)
        g_scale[b] = 1.0f / ((float)nsrc * 0.4f);
}

// K4: materialize output. One block per 16 rows; per-thread column data
// (y8, xm for its 8 columns) lives in registers and is reused across rows.
// out[b,i,j] = (xm[j]+ym[i] > 0 && x8_i+y8_j > 0) ? sc * tanh(x8_i + y8_j) : 0
#define TR 16
__global__ void __launch_bounds__(256) k_out(float* __restrict__ out) {
    int b    = blockIdx.x >> 7;      // N/TR = 128 tiles per batch
    int tile = blockIdx.x & 127;
    int row0 = b * N + tile * TR;

    const float4* y4  = reinterpret_cast<const float4*>(g_y8 + b * N);
    const float4* xm4 = reinterpret_cast<const float4*>(g_xm + b * N);
    int t0 = threadIdx.x, t1 = threadIdx.x + 256;
    float4 yA  = y4[t0],  yB  = y4[t1];
    float4 xmA = xm4[t0], xmB = xm4[t1];
    float sc = g_scale[b];

    __shared__ float s_x[TR], s_ym[TR];
    if (threadIdx.x < TR)
        s_x[threadIdx.x] = g_x8[row0 + threadIdx.x];
    else if (threadIdx.x < 2 * TR)
        s_ym[threadIdx.x - TR] = g_ym[row0 + threadIdx.x - TR];
    __syncthreads();

#pragma unroll 4
    for (int r = 0; r < TR; r++) {
        float xi  = s_x[r];
        float ymi = s_ym[r];
        float4* o4 = reinterpret_cast<float4*>(out + (size_t)(row0 + r) * N);

        float4 rA, rB;
        {
            float e0 = xi + yA.x, e1 = xi + yA.y, e2 = xi + yA.z, e3 = xi + yA.w;
            rA.x = (fminf(e0, xmA.x + ymi) > 0.f) ? sc * tanh_fast(e0) : 0.f;
            rA.y = (fminf(e1, xmA.y + ymi) > 0.f) ? sc * tanh_fast(e1) : 0.f;
            rA.z = (fminf(e2, xmA.z + ymi) > 0.f) ? sc * tanh_fast(e2) : 0.f;
            rA.w = (fminf(e3, xmA.w + ymi) > 0.f) ? sc * tanh_fast(e3) : 0.f;
        }
        {
            float e0 = xi + yB.x, e1 = xi + yB.y, e2 = xi + yB.z, e3 = xi + yB.w;
            rB.x = (fminf(e0, xmB.x + ymi) > 0.f) ? sc * tanh_fast(e0) : 0.f;
            rB.y = (fminf(e1, xmB.y + ymi) > 0.f) ? sc * tanh_fast(e1) : 0.f;
            rB.z = (fminf(e2, xmB.z + ymi) > 0.f) ? sc * tanh_fast(e2) : 0.f;
            rB.w = (fminf(e3, xmB.w + ymi) > 0.f) ? sc * tanh_fast(e3) : 0.f;
        }
        o4[t0] = rA;
        o4[t1] = rB;
    }
}

extern "C" void kernel_launch(void* const* d_in, const int* in_sizes, int n_in,
                              void* d_out, int out_size) {
    const float* emb1  = (const float*)d_in[0];
    const float* W     = (const float*)d_in[1];
    const float* a1    = (const float*)d_in[2];
    const float* a2    = (const float*)d_in[3];
    const int*   n_src = (const int*)d_in[4];
    const int*   nstgt = (const int*)d_in[5];
    float* out = (float*)d_out;

    k_wproj<<<16, 128>>>(W, a1, a2);
    k_xy<<<(B * N * 32 + 255) / 256, 256>>>(emb1);
    k_select<<<dim3(N / 64, B), 256>>>(n_src, nstgt);
    k_out<<<B * (N / TR), 256>>>(out);
}

// round 5
// speedup vs baseline: 1.6492x; 1.0414x over previous
#include <cuda_runtime.h>
#include <cstdint>

// Problem constants (fixed by the dataset)
#define B 8
#define N 2048
#define IN_F 512
#define OUT_F 128

// Scratch (allocation-free rule: __device__ globals), 16B-aligned for float4
__device__ __align__(16) float g_w1[IN_F];
__device__ __align__(16) float g_w2[IN_F];
__device__ __align__(16) float g_x8[B * N];   // 0.125 * (emb1[b,i,:] . w1)
__device__ __align__(16) float g_y8[B * N];   // 0.125 * (emb1[b,i,:] . w2)
__device__ __align__(16) float g_xm[B * N];   // act ? x8 : -1e30
__device__ __align__(16) float g_ym[B * N];   // act ? y8 : -1e30
__device__ float g_scale[B];

__device__ __forceinline__ float tanh_fast(float x) {
    float r;
    asm("tanh.approx.f32 %0, %1;" : "=f"(r) : "f"(x));
    return r;
}

// K1: w1 = W^T a1, w2 = W^T a2.  W is [OUT_F, IN_F] row-major.
// grid 16, block 256: f = bid*32 + lane, o-dim split 8 ways across warps.
__global__ void __launch_bounds__(256) k_wproj(const float* __restrict__ W,
                                               const float* __restrict__ a1,
                                               const float* __restrict__ a2) {
    int lane = threadIdx.x & 31;
    int oq   = threadIdx.x >> 5;                 // 0..7
    int f    = blockIdx.x * 32 + lane;           // 0..511
    float s1 = 0.f, s2 = 0.f;
#pragma unroll
    for (int o = oq * 16; o < oq * 16 + 16; o++) {
        float w = __ldg(W + (size_t)o * IN_F + f);
        s1 = fmaf(w, __ldg(a1 + o), s1);
        s2 = fmaf(w, __ldg(a2 + o), s2);
    }
    __shared__ float p1[256], p2[256];
    p1[threadIdx.x] = s1;
    p2[threadIdx.x] = s2;
    __syncthreads();
    if (threadIdx.x < 32) {
        float r1 = 0.f, r2 = 0.f;
#pragma unroll
        for (int c = 0; c < 8; c++) {
            r1 += p1[lane + 32 * c];
            r2 += p2[lane + 32 * c];
        }
        g_w1[f] = r1;
        g_w2[f] = r2;
    }
}

// K2: per-warp dual dot products, 4 rows per warp (MLP=16 emb loads in flight),
// w1/w2 held in registers. Stored pre-scaled by 0.125 (exact pow2).
#define RPW 4
__global__ void __launch_bounds__(256) k_xy(const float* __restrict__ emb) {
    int warp = (blockIdx.x * blockDim.x + threadIdx.x) >> 5;
    int lane = threadIdx.x & 31;
    int row0 = warp * RPW;                     // 4096 warps cover 16384 rows

    const float4* w1 = reinterpret_cast<const float4*>(g_w1);
    const float4* w2 = reinterpret_cast<const float4*>(g_w2);
    float4 W1[4], W2[4];
#pragma unroll
    for (int k = 0; k < 4; k++) {
        W1[k] = w1[lane + 32 * k];
        W2[k] = w2[lane + 32 * k];
    }

    float s1[RPW], s2[RPW];
#pragma unroll
    for (int r = 0; r < RPW; r++) { s1[r] = 0.f; s2[r] = 0.f; }

#pragma unroll
    for (int r = 0; r < RPW; r++) {
        const float4* row = reinterpret_cast<const float4*>(emb + (size_t)(row0 + r) * IN_F);
#pragma unroll
        for (int k = 0; k < 4; k++) {
            float4 e = row[lane + 32 * k];
            s1[r] = fmaf(e.x, W1[k].x, fmaf(e.y, W1[k].y, fmaf(e.z, W1[k].z, fmaf(e.w, W1[k].w, s1[r]))));
            s2[r] = fmaf(e.x, W2[k].x, fmaf(e.y, W2[k].y, fmaf(e.z, W2[k].z, fmaf(e.w, W2[k].w, s2[r]))));
        }
    }
#pragma unroll
    for (int off = 16; off; off >>= 1) {
#pragma unroll
        for (int r = 0; r < RPW; r++) {
            s1[r] += __shfl_down_sync(0xffffffffu, s1[r], off);
            s2[r] += __shfl_down_sync(0xffffffffu, s2[r], off);
        }
    }
    if (lane == 0) {
#pragma unroll
        for (int r = 0; r < RPW; r++) {
            g_x8[row0 + r] = s1[r] * 0.125f;
            g_y8[row0 + r] = s2[r] * 0.125f;
        }
    }
}

// K3: stable descending rank of y among valid columns; sentinel arrays.
// grid (N/64, B), block 256: 4 threads per column j, float4 smem scan.
__global__ void __launch_bounds__(256) k_select(const int* __restrict__ n_src,
                                                const int* __restrict__ ns_tgt) {
    int b = blockIdx.y;
    __shared__ __align__(16) float ys[N];
    int ns   = ns_tgt[b];
    int nsrc = n_src[b];
    int kb   = (int)((float)nsrc * 0.4f);   // float32 mul + trunc, matches ref

    const float4* src4 = reinterpret_cast<const float4*>(g_y8 + b * N);
    float4* ys4 = reinterpret_cast<float4*>(ys);
    for (int l = threadIdx.x; l < N / 4; l += 256)
        ys4[l] = src4[l];
    __syncthreads();

    int q  = threadIdx.x & 3;
    int jj = threadIdx.x >> 2;               // 0..63
    int j  = blockIdx.x * 64 + jj;
    float yj = ys[j];
    int cnt = 0;
#pragma unroll 4
    for (int l4 = q; l4 < N / 4; l4 += 4) {
        float4 v = ys4[l4];
        int l = l4 * 4;
        cnt += (l     < ns) && ((v.x > yj) || ((v.x == yj) && (l     < j)));
        cnt += (l + 1 < ns) && ((v.y > yj) || ((v.y == yj) && (l + 1 < j)));
        cnt += (l + 2 < ns) && ((v.z > yj) || ((v.z == yj) && (l + 2 < j)));
        cnt += (l + 3 < ns) && ((v.w > yj) || ((v.w == yj) && (l + 3 < j)));
    }
    // combine the 4 partial counts (lanes jj*4+q are consecutive in the warp)
    cnt += __shfl_xor_sync(0xffffffffu, cnt, 1);
    cnt += __shfl_xor_sync(0xffffffffu, cnt, 2);

    if (q == 0) {
        bool act = (j < ns) && (cnt < kb) && (j < nsrc);
        float xj = g_x8[b * N + j];
        g_xm[b * N + j] = act ? xj : -1e30f;
        g_ym[b * N + j] = act ? yj : -1e30f;
    }
    if (blockIdx.x == 0 && threadIdx.x == 0)
        g_scale[b] = 1.0f / ((float)nsrc * 0.4f);
}

// K4: materialize output. One block per 16 rows; per-thread column data
// (y8, xm for its 8 columns) lives in registers and is reused across rows.
// out[b,i,j] = (xm[j]+ym[i] > 0 && x8_i+y8_j > 0) ? sc * tanh(x8_i + y8_j) : 0
#define TR 16
__global__ void __launch_bounds__(256) k_out(float* __restrict__ out) {
    int b    = blockIdx.x >> 7;      // N/TR = 128 tiles per batch
    int tile = blockIdx.x & 127;
    int row0 = b * N + tile * TR;

    const float4* y4  = reinterpret_cast<const float4*>(g_y8 + b * N);
    const float4* xm4 = reinterpret_cast<const float4*>(g_xm + b * N);
    int t0 = threadIdx.x, t1 = threadIdx.x + 256;
    float4 yA  = y4[t0],  yB  = y4[t1];
    float4 xmA = xm4[t0], xmB = xm4[t1];
    float sc = g_scale[b];

    __shared__ float s_x[TR], s_ym[TR];
    if (threadIdx.x < TR)
        s_x[threadIdx.x] = g_x8[row0 + threadIdx.x];
    else if (threadIdx.x < 2 * TR)
        s_ym[threadIdx.x - TR] = g_ym[row0 + threadIdx.x - TR];
    __syncthreads();

#pragma unroll 4
    for (int r = 0; r < TR; r++) {
        float xi  = s_x[r];
        float ymi = s_ym[r];
        float4* o4 = reinterpret_cast<float4*>(out + (size_t)(row0 + r) * N);

        float4 rA, rB;
        {
            float e0 = xi + yA.x, e1 = xi + yA.y, e2 = xi + yA.z, e3 = xi + yA.w;
            rA.x = (fminf(e0, xmA.x + ymi) > 0.f) ? sc * tanh_fast(e0) : 0.f;
            rA.y = (fminf(e1, xmA.y + ymi) > 0.f) ? sc * tanh_fast(e1) : 0.f;
            rA.z = (fminf(e2, xmA.z + ymi) > 0.f) ? sc * tanh_fast(e2) : 0.f;
            rA.w = (fminf(e3, xmA.w + ymi) > 0.f) ? sc * tanh_fast(e3) : 0.f;
        }
        {
            float e0 = xi + yB.x, e1 = xi + yB.y, e2 = xi + yB.z, e3 = xi + yB.w;
            rB.x = (fminf(e0, xmB.x + ymi) > 0.f) ? sc * tanh_fast(e0) : 0.f;
            rB.y = (fminf(e1, xmB.y + ymi) > 0.f) ? sc * tanh_fast(e1) : 0.f;
            rB.z = (fminf(e2, xmB.z + ymi) > 0.f) ? sc * tanh_fast(e2) : 0.f;
            rB.w = (fminf(e3, xmB.w + ymi) > 0.f) ? sc * tanh_fast(e3) : 0.f;
        }
        __stcs(&o4[t0], rA);   // streaming store: output >> L2, evict-first
        __stcs(&o4[t1], rB);
    }
}

extern "C" void kernel_launch(void* const* d_in, const int* in_sizes, int n_in,
                              void* d_out, int out_size) {
    const float* emb1  = (const float*)d_in[0];
    const float* W     = (const float*)d_in[1];
    const float* a1    = (const float*)d_in[2];
    const float* a2    = (const float*)d_in[3];
    const int*   n_src = (const int*)d_in[4];
    const int*   nstgt = (const int*)d_in[5];
    float* out = (float*)d_out;

    k_wproj<<<16, 256>>>(W, a1, a2);
    k_xy<<<(B * N / RPW) / 8, 256>>>(emb1);          // 4096 warps, 512 blocks
    k_select<<<dim3(N / 64, B), 256>>>(n_src, nstgt);
    k_out<<<B * (N / TR), 256>>>(out);
}